// round 10
// baseline (speedup 1.0000x reference)
#include <cuda_runtime.h>
#include <cuda_fp16.h>
#include <cstdint>

#define B_ 8
#define L_ 2048
#define H_ 1024

// Scratch: __device__ globals (no cudaMalloc allowed anywhere)
__device__ __half g_xh[(size_t)B_ * L_ * H_];        // 32 MB  fp16 x
__device__ __half g_wh[(size_t)3 * H_ * H_];         // 6 MB   fp16 Wq|Wk|Wv (row-concat)
__device__ float  g_bias[3 * H_];                    // packed bq|bk|bv
__device__ __half g_qkv[(size_t)B_ * L_ * 3 * H_];   // 96 MB  fused q|k|v per row
__device__ __half g_e[(size_t)B_ * L_ * L_];         // 64 MB  exp(scores), diag=0
__device__ float  g_rs[(size_t)B_ * L_];             // 64 KB  1/rowsum

// ---- fp16 mma.sync m16n8k16 GEMM: block 128x128, 4 warps (2x2) of 64x64,
// ---- BK=32, 4-stage cp.async, ldmatrix.x4 (+ .trans for N-major B).
#define BMT 128
#define BNT 128
#define BKT 32
#define STAGES 4
#define SAH 40    // K-major smem row stride (halves): conflict-free ldmatrix
#define SBH 136   // N-major smem row stride (halves): conflict-free trans ldmatrix

#define A_STAGE_B (BMT * SAH * 2)                // 10240 bytes (also used for B)
#define NT_SMEM (STAGES * 2 * A_STAGE_B)         // 81920

__device__ __forceinline__ uint32_t smem_u32(const void* p) {
    uint32_t a;
    asm("{ .reg .u64 t; cvta.to.shared.u64 t, %1; cvt.u32.u64 %0, t; }" : "=r"(a) : "l"(p));
    return a;
}
__device__ __forceinline__ void cp16(uint32_t dst, const void* src) {
    asm volatile("cp.async.cg.shared.global [%0], [%1], 16;" :: "r"(dst), "l"(src));
}
#define CP_COMMIT() asm volatile("cp.async.commit_group;" ::: "memory")
#define CP_WAIT2()  asm volatile("cp.async.wait_group 2;" ::: "memory")

#define LDSM_X4(d0, d1, d2, d3, addr)                                            \
    asm volatile("ldmatrix.sync.aligned.m8n8.x4.shared.b16 {%0,%1,%2,%3}, [%4];" \
        : "=r"(d0), "=r"(d1), "=r"(d2), "=r"(d3) : "r"(addr))
#define LDSM_X4_T(d0, d1, d2, d3, addr)                                          \
    asm volatile("ldmatrix.sync.aligned.m8n8.x4.trans.shared.b16 {%0,%1,%2,%3}, [%4];" \
        : "=r"(d0), "=r"(d1), "=r"(d2), "=r"(d3) : "r"(addr))

__device__ __forceinline__ void mma_f16(float& d0, float& d1, float& d2, float& d3,
                                        unsigned a0, unsigned a1, unsigned a2, unsigned a3,
                                        unsigned b0, unsigned b1) {
    asm volatile(
        "mma.sync.aligned.m16n8k16.row.col.f32.f16.f16.f32 "
        "{%0,%1,%2,%3}, {%4,%5,%6,%7}, {%8,%9}, {%0,%1,%2,%3};\n"
        : "+f"(d0), "+f"(d1), "+f"(d2), "+f"(d3)
        : "r"(a0), "r"(a1), "r"(a2), "r"(a3), "r"(b0), "r"(b1));
}

// C[M,N] = post( sc(col)*(A[M,K]*op(B) + bias) )
//  bTrans=0: B is [N][K] K-contiguous.  bTrans=1: B is [K][N] N-contiguous.
//  sc(col) = (col < splitCol) ? scale0 : scale1.
//  Ch path: if expOut, v = (diagZero && row==col) ? 0 : exp(v); store f16.
//  Cf path: if rowScale, v *= rowScale[bz*M + row]; store f32.
__global__ __launch_bounds__(128, 2) void gemm_h(
    const __half* __restrict__ A, const __half* __restrict__ Bm,
    const float* __restrict__ bias, __half* __restrict__ Ch, float* __restrict__ Cf,
    const float* __restrict__ rowScale,
    int M, int N, int K, int lda, int ldb, int ldc,
    float scale0, int splitCol, float scale1, int expOut, int bTrans,
    long long sA, long long sB, long long sC)
{
    extern __shared__ char sm[];
    const uint32_t smb = smem_u32(sm);

    A  += (long long)blockIdx.z * sA;
    Bm += (long long)blockIdx.z * sB;
    if (Ch) Ch += (long long)blockIdx.z * sC;
    if (Cf) Cf += (long long)blockIdx.z * sC;

    const int tid  = threadIdx.x;
    const int warp = tid >> 5;
    const int lane = tid & 31;
    const int lq = lane >> 2, lr = lane & 3;
    const int wm = warp >> 1, wn = warp & 1;        // 2x2 warps, 64x64 each
    const int rowBase = blockIdx.y * BMT;
    const int colBase = blockIdx.x * BNT;

    const uint32_t aBase = smb;
    const uint32_t bBase = smb + STAGES * A_STAGE_B;

    const int g  = lane >> 3;      // 0..3
    const int r8 = lane & 7;
    uint32_t aoff[4], boff[4];
#pragma unroll
    for (int mt = 0; mt < 4; mt++)   // A x4: m0=(r,k0) m1=(r+8,k0) m2=(r,k8) m3=(r+8,k8)
        aoff[mt] = (uint32_t)((wm * 64 + mt * 16 + (g & 1) * 8 + r8) * (SAH * 2) + (g >> 1) * 16);
    if (!bTrans) {
#pragma unroll
        for (int p = 0; p < 4; p++)  // B x4: m0=(n,k0) m1=(n,k8) m2=(n+8,k0) m3=(n+8,k8)
            boff[p] = (uint32_t)((wn * 64 + p * 16 + (g >> 1) * 8 + r8) * (SAH * 2) + (g & 1) * 16);
    } else {
#pragma unroll
        for (int p = 0; p < 4; p++)  // trans variant
            boff[p] = (uint32_t)(((g & 1) * 8 + r8) * (SBH * 2) + (wn * 64 + p * 16 + (g >> 1) * 8) * 2);
    }

    auto stage = [&](int kc, int st) {
        const int koff = kc * BKT;
        const uint32_t aso = aBase + st * A_STAGE_B;
        const uint32_t bso = bBase + st * A_STAGE_B;
#pragma unroll
        for (int i = 0; i < 4; i++) {
            const int f = i * 128 + tid;
            const int arow = f >> 2, ak4 = f & 3;
            cp16(aso + arow * (SAH * 2) + ak4 * 16,
                 A + (long long)(rowBase + arow) * lda + koff + ak4 * 8);
            if (!bTrans) {
                cp16(bso + arow * (SAH * 2) + ak4 * 16,
                     Bm + (long long)(colBase + arow) * ldb + koff + ak4 * 8);
            } else {
                const int brow = f >> 4, bc4 = f & 15;
                cp16(bso + brow * (SBH * 2) + bc4 * 16,
                     Bm + (long long)(koff + brow) * ldb + colBase + bc4 * 8);
            }
        }
    };

    float acc[4][8][4];
#pragma unroll
    for (int i = 0; i < 4; i++)
#pragma unroll
        for (int j = 0; j < 8; j++)
#pragma unroll
            for (int r = 0; r < 4; r++) acc[i][j][r] = 0.0f;

    const int NC = K / BKT;
    stage(0, 0); CP_COMMIT();
    stage(1, 1); CP_COMMIT();
    stage(2, 2); CP_COMMIT();

    int bufC = 0, bufS = 3;
    for (int c = 0; c < NC; c++) {
        CP_WAIT2();
        __syncthreads();
        if (c + 3 < NC) stage(c + 3, bufS);
        CP_COMMIT();

        const uint32_t aS = aBase + bufC * A_STAGE_B;
        const uint32_t bS = bBase + bufC * A_STAGE_B;
#pragma unroll
        for (int ks = 0; ks < 2; ks++) {
            unsigned af[4][4], bf[8][2];
#pragma unroll
            for (int mt = 0; mt < 4; mt++)
                LDSM_X4(af[mt][0], af[mt][1], af[mt][2], af[mt][3],
                        aS + aoff[mt] + (uint32_t)(ks * 32));
            if (!bTrans) {
#pragma unroll
                for (int p = 0; p < 4; p++)
                    LDSM_X4(bf[2*p][0], bf[2*p][1], bf[2*p+1][0], bf[2*p+1][1],
                            bS + boff[p] + (uint32_t)(ks * 32));
            } else {
#pragma unroll
                for (int p = 0; p < 4; p++)
                    LDSM_X4_T(bf[2*p][0], bf[2*p][1], bf[2*p+1][0], bf[2*p+1][1],
                              bS + boff[p] + (uint32_t)(ks * 16 * (SBH * 2)));
            }
#pragma unroll
            for (int mt = 0; mt < 4; mt++)
#pragma unroll
                for (int nt = 0; nt < 8; nt++)
                    mma_f16(acc[mt][nt][0], acc[mt][nt][1], acc[mt][nt][2], acc[mt][nt][3],
                            af[mt][0], af[mt][1], af[mt][2], af[mt][3],
                            bf[nt][0], bf[nt][1]);
        }
        bufC = (bufC == STAGES - 1) ? 0 : bufC + 1;
        bufS = (bufS == STAGES - 1) ? 0 : bufS + 1;
    }

#pragma unroll
    for (int mt = 0; mt < 4; mt++) {
        const int row = rowBase + wm * 64 + mt * 16 + lq;
#pragma unroll
        for (int nt = 0; nt < 8; nt++) {
            const int col = colBase + wn * 64 + nt * 8 + 2 * lr;
            float v0 = acc[mt][nt][0], v1 = acc[mt][nt][1];
            float v2 = acc[mt][nt][2], v3 = acc[mt][nt][3];
            if (bias) { v0 += bias[col]; v1 += bias[col + 1]; v2 += bias[col]; v3 += bias[col + 1]; }
            const float s0 = (col     < splitCol) ? scale0 : scale1;
            const float s1 = (col + 1 < splitCol) ? scale0 : scale1;
            v0 *= s0; v1 *= s1; v2 *= s0; v3 *= s1;
            if (Ch) {
                if (expOut) {
                    // e = exp(s); diagonal -> exact 0 (softmax excludes self).
                    v0 = (row == col)         ? 0.0f : __expf(v0);
                    v1 = (row == col + 1)     ? 0.0f : __expf(v1);
                    v2 = (row + 8 == col)     ? 0.0f : __expf(v2);
                    v3 = (row + 8 == col + 1) ? 0.0f : __expf(v3);
                }
                *(__half2*)&Ch[(long long)row * ldc + col]       = __floats2half2_rn(v0, v1);
                *(__half2*)&Ch[(long long)(row + 8) * ldc + col] = __floats2half2_rn(v2, v3);
            } else {
                if (rowScale) {
                    const float r0 = __ldg(&rowScale[(long long)blockIdx.z * M + row]);
                    const float r1 = __ldg(&rowScale[(long long)blockIdx.z * M + row + 8]);
                    v0 *= r0; v1 *= r0; v2 *= r1; v3 *= r1;
                }
                *(float2*)&Cf[(long long)row * ldc + col]       = make_float2(v0, v1);
                *(float2*)&Cf[(long long)(row + 8) * ldc + col] = make_float2(v2, v3);
            }
        }
    }
}

// 1/rowsum of E (f16), one block per row.
__global__ __launch_bounds__(256) void rowsum_recip(const __half* __restrict__ E,
                                                    float* __restrict__ rs)
{
    __shared__ float red[256];
    const __half* row = E + (long long)blockIdx.x * L_;
    const int tid = threadIdx.x;
    float lsum = 0.0f;
#pragma unroll
    for (int i = 0; i < 4; i++) {
        const __half2 h = ((const __half2*)row)[tid + i * 256];
        const float2 f = __half22float2(h);
        lsum += f.x + f.y;
    }
    red[tid] = lsum;
    __syncthreads();
    for (int s = 128; s > 0; s >>= 1) {
        if (tid < s) red[tid] += red[tid + s];
        __syncthreads();
    }
    if (tid == 0) rs[blockIdx.x] = 1.0f / red[0];
}

// Round f32 -> fp16 (rne). Grid-stride, float4 in / 4x half out.
__global__ __launch_bounds__(256) void round_f16(const float* __restrict__ in,
                                                 __half* __restrict__ out, long long n4)
{
    const long long i0 = (long long)blockIdx.x * blockDim.x + threadIdx.x;
    const long long stride = (long long)gridDim.x * blockDim.x;
    for (long long i = i0; i < n4; i += stride) {
        float4 v = ((const float4*)in)[i];
        __half2 h0 = __floats2half2_rn(v.x, v.y);
        __half2 h1 = __floats2half2_rn(v.z, v.w);
        ((uint2*)out)[i] = make_uint2(*(uint32_t*)&h0, *(uint32_t*)&h1);
    }
}

// Round all three weight matrices + pack biases in one launch.
__global__ __launch_bounds__(256) void prep_w(
    const float* __restrict__ Wq, const float* __restrict__ Wk, const float* __restrict__ Wv,
    const float* __restrict__ bq, const float* __restrict__ bk, const float* __restrict__ bv,
    __half* __restrict__ wh, float* __restrict__ bias)
{
    const long long seg4 = (long long)H_ * H_ / 4;
    const long long i0 = (long long)blockIdx.x * blockDim.x + threadIdx.x;
    const long long stride = (long long)gridDim.x * blockDim.x;
    for (long long i = i0; i < 3 * seg4; i += stride) {
        const int seg = (int)(i / seg4);
        const long long loc = i - (long long)seg * seg4;
        const float* src = (seg == 0) ? Wq : (seg == 1) ? Wk : Wv;
        float4 v = ((const float4*)src)[loc];
        __half2 h0 = __floats2half2_rn(v.x, v.y);
        __half2 h1 = __floats2half2_rn(v.z, v.w);
        ((uint2*)wh)[i] = make_uint2(*(uint32_t*)&h0, *(uint32_t*)&h1);
    }
    const int bi = blockIdx.x * blockDim.x + threadIdx.x;
    if (bi < H_)            bias[bi] = bq[bi];
    else if (bi < 2 * H_)   bias[bi] = bk[bi - H_];
    else if (bi < 3 * H_)   bias[bi] = bv[bi - 2 * H_];
}

extern "C" void kernel_launch(void* const* d_in, const int* in_sizes, int n_in,
                              void* d_out, int out_size)
{
    const float* x  = (const float*)d_in[0];
    const float* Wq = (const float*)d_in[1];
    const float* bq = (const float*)d_in[2];
    const float* Wk = (const float*)d_in[3];
    const float* bk = (const float*)d_in[4];
    const float* Wv = (const float*)d_in[5];
    const float* bv = (const float*)d_in[6];
    float* out = (float*)d_out;

    __half *xh, *wh, *qkv, *e;
    float *bias, *rs;
    cudaGetSymbolAddress((void**)&xh,   g_xh);
    cudaGetSymbolAddress((void**)&wh,   g_wh);
    cudaGetSymbolAddress((void**)&qkv,  g_qkv);
    cudaGetSymbolAddress((void**)&e,    g_e);
    cudaGetSymbolAddress((void**)&bias, g_bias);
    cudaGetSymbolAddress((void**)&rs,   g_rs);

    cudaFuncSetAttribute(gemm_h, cudaFuncAttributeMaxDynamicSharedMemorySize, NT_SMEM);

    const long long sQKV = (long long)L_ * 3 * H_;
    const long long sSS  = (long long)L_ * L_;
    const long long sO   = (long long)L_ * H_;

    // Input prep: x -> fp16; Wq|Wk|Wv -> fp16 concat + bias pack (one launch).
    round_f16<<<1024, 256>>>(x, xh, (long long)B_ * L_ * H_ / 4);
    prep_w<<<768, 256>>>(Wq, Wk, Wv, bq, bk, bv, wh, bias);

    const dim3 blk(128);

    // Fused QKV: qkv[r][0:H]=q (scaled 1/H), [H:2H]=k, [2H:3H]=v
    dim3 gQKV(3 * H_ / BNT, (B_ * L_) / BMT, 1);
    gemm_h<<<gQKV, blk, NT_SMEM>>>(xh, wh, bias, qkv, nullptr, nullptr,
                                   B_ * L_, 3 * H_, H_, H_, H_, 3 * H_,
                                   1.0f / (float)H_, H_, 1.0f, 0, 0, 0, 0, 0);

    // E[b] = exp(q[b]*k[b]^T), diag=0, f16 out. (no max-shift needed: |s|<~0.2)
    dim3 gS(L_ / BNT, L_ / BMT, B_);
    gemm_h<<<gS, blk, NT_SMEM>>>(qkv, qkv + H_, nullptr, e, nullptr, nullptr,
                                 L_, L_, H_, 3 * H_, 3 * H_, L_,
                                 1.0f, 0, 1.0f, 1, 0, sQKV, sQKV, sSS);

    // 1/rowsum
    rowsum_recip<<<B_ * L_, 256>>>(e, rs);

    // out[b] = (E[b] * V[b]) * (1/rowsum)  (V N-major, trans-ldmatrix path)
    dim3 gO(H_ / BNT, L_ / BMT, B_);
    gemm_h<<<gO, blk, NT_SMEM>>>(e, qkv + 2 * H_, nullptr, nullptr, out, rs,
                                 L_, H_, L_, L_, 3 * H_, H_,
                                 1.0f, 0, 1.0f, 0, 1, sSS, sQKV, sO);
}

// round 11
// speedup vs baseline: 1.0750x; 1.0750x over previous
#include <cuda_runtime.h>
#include <cuda_fp16.h>
#include <cstdint>

#define B_ 8
#define L_ 2048
#define H_ 1024

// Scratch: __device__ globals (no cudaMalloc allowed anywhere)
__device__ __half g_xh[(size_t)B_ * L_ * H_];        // 32 MB  fp16 x
__device__ __half g_wh[(size_t)3 * H_ * H_];         // 6 MB   fp16 Wq|Wk|Wv (row-concat)
__device__ float  g_bias[3 * H_];                    // packed bq|bk|bv
__device__ __half g_qkv[(size_t)B_ * L_ * 3 * H_];   // 96 MB  fused q|k|v per row
__device__ __half g_e[(size_t)B_ * L_ * L_];         // 64 MB  exp(scores), diag=0
__device__ float  g_rsp[(size_t)32 * B_ * L_];       // 2 MB   partial row sums
__device__ float  g_rs[(size_t)B_ * L_];             // 64 KB  1/rowsum

// ---- fp16 mma.sync m16n8k16 GEMM: block 128x128, 4 warps (2x2) of 64x64,
// ---- BK=32, 4-stage cp.async, ldmatrix.x4 (+ .trans for N-major B).
#define BMT 128
#define BNT 128
#define BKT 32
#define STAGES 4
#define SAH 40    // K-major smem row stride (halves): conflict-free ldmatrix
#define SBH 136   // N-major smem row stride (halves): conflict-free trans ldmatrix

#define A_STAGE_B (BMT * SAH * 2)                // 10240 bytes (also used for B)
#define NT_SMEM (STAGES * 2 * A_STAGE_B)         // 81920

// MODE for the templated GEMM
#define MODE_QKV 0   // half out, bias, split col scale
#define MODE_EXP 1   // exp(v), diag->0, half out + partial row sums
#define MODE_AV  2   // f32 out, multiply by rowScale (reciprocal)

__device__ __forceinline__ uint32_t smem_u32(const void* p) {
    uint32_t a;
    asm("{ .reg .u64 t; cvta.to.shared.u64 t, %1; cvt.u32.u64 %0, t; }" : "=r"(a) : "l"(p));
    return a;
}
__device__ __forceinline__ void cp16(uint32_t dst, const void* src) {
    asm volatile("cp.async.cg.shared.global [%0], [%1], 16;" :: "r"(dst), "l"(src));
}
#define CP_COMMIT() asm volatile("cp.async.commit_group;" ::: "memory")
#define CP_WAIT2()  asm volatile("cp.async.wait_group 2;" ::: "memory")

#define LDSM_X4(d0, d1, d2, d3, addr)                                            \
    asm volatile("ldmatrix.sync.aligned.m8n8.x4.shared.b16 {%0,%1,%2,%3}, [%4];" \
        : "=r"(d0), "=r"(d1), "=r"(d2), "=r"(d3) : "r"(addr))
#define LDSM_X4_T(d0, d1, d2, d3, addr)                                          \
    asm volatile("ldmatrix.sync.aligned.m8n8.x4.trans.shared.b16 {%0,%1,%2,%3}, [%4];" \
        : "=r"(d0), "=r"(d1), "=r"(d2), "=r"(d3) : "r"(addr))

__device__ __forceinline__ void mma_f16(float& d0, float& d1, float& d2, float& d3,
                                        unsigned a0, unsigned a1, unsigned a2, unsigned a3,
                                        unsigned b0, unsigned b1) {
    asm volatile(
        "mma.sync.aligned.m16n8k16.row.col.f32.f16.f16.f32 "
        "{%0,%1,%2,%3}, {%4,%5,%6,%7}, {%8,%9}, {%0,%1,%2,%3};\n"
        : "+f"(d0), "+f"(d1), "+f"(d2), "+f"(d3)
        : "r"(a0), "r"(a1), "r"(a2), "r"(a3), "r"(b0), "r"(b1));
}

// Templated GEMM. BTRANS=0: B is [N][K] K-contiguous. BTRANS=1: B is [K][N].
template <int MODE, int BTRANS>
__global__ __launch_bounds__(128, 2) void gemm_t(
    const __half* __restrict__ A, const __half* __restrict__ Bm,
    const float* __restrict__ bias, __half* __restrict__ Ch, float* __restrict__ Cf,
    const float* __restrict__ rowScale, float* __restrict__ rsp,
    int M, int N, int K, int lda, int ldb, int ldc,
    float scale0, int splitCol, float scale1,
    long long sA, long long sB, long long sC)
{
    extern __shared__ char sm[];
    const uint32_t smb = smem_u32(sm);

    A  += (long long)blockIdx.z * sA;
    Bm += (long long)blockIdx.z * sB;
    if (MODE == MODE_AV) Cf += (long long)blockIdx.z * sC;
    else                 Ch += (long long)blockIdx.z * sC;

    const int tid  = threadIdx.x;
    const int warp = tid >> 5;
    const int lane = tid & 31;
    const int lq = lane >> 2, lr = lane & 3;
    const int wm = warp >> 1, wn = warp & 1;        // 2x2 warps, 64x64 each
    const int rowBase = blockIdx.y * BMT;
    const int colBase = blockIdx.x * BNT;

    const uint32_t aBase = smb;
    const uint32_t bBase = smb + STAGES * A_STAGE_B;

    const int g  = lane >> 3;
    const int r8 = lane & 7;
    uint32_t aoff[4], boff[4];
#pragma unroll
    for (int mt = 0; mt < 4; mt++)   // A x4: m0=(r,k0) m1=(r+8,k0) m2=(r,k8) m3=(r+8,k8)
        aoff[mt] = (uint32_t)((wm * 64 + mt * 16 + (g & 1) * 8 + r8) * (SAH * 2) + (g >> 1) * 16);
    if (!BTRANS) {
#pragma unroll
        for (int p = 0; p < 4; p++)
            boff[p] = (uint32_t)((wn * 64 + p * 16 + (g >> 1) * 8 + r8) * (SAH * 2) + (g & 1) * 16);
    } else {
#pragma unroll
        for (int p = 0; p < 4; p++)
            boff[p] = (uint32_t)(((g & 1) * 8 + r8) * (SBH * 2) + (wn * 64 + p * 16 + (g >> 1) * 8) * 2);
    }

    auto stage = [&](int kc, int st) {
        const int koff = kc * BKT;
        const uint32_t aso = aBase + st * A_STAGE_B;
        const uint32_t bso = bBase + st * A_STAGE_B;
#pragma unroll
        for (int i = 0; i < 4; i++) {
            const int f = i * 128 + tid;
            const int arow = f >> 2, ak4 = f & 3;
            cp16(aso + arow * (SAH * 2) + ak4 * 16,
                 A + (long long)(rowBase + arow) * lda + koff + ak4 * 8);
            if (!BTRANS) {
                cp16(bso + arow * (SAH * 2) + ak4 * 16,
                     Bm + (long long)(colBase + arow) * ldb + koff + ak4 * 8);
            } else {
                const int brow = f >> 4, bc4 = f & 15;
                cp16(bso + brow * (SBH * 2) + bc4 * 16,
                     Bm + (long long)(koff + brow) * ldb + colBase + bc4 * 8);
            }
        }
    };

    float acc[4][8][4];
#pragma unroll
    for (int i = 0; i < 4; i++)
#pragma unroll
        for (int j = 0; j < 8; j++)
#pragma unroll
            for (int r = 0; r < 4; r++) acc[i][j][r] = 0.0f;

    const int NC = K / BKT;
    stage(0, 0); CP_COMMIT();
    stage(1, 1); CP_COMMIT();
    stage(2, 2); CP_COMMIT();

    int bufC = 0, bufS = 3;
    for (int c = 0; c < NC; c++) {
        CP_WAIT2();
        __syncthreads();
        if (c + 3 < NC) stage(c + 3, bufS);
        CP_COMMIT();

        const uint32_t aS = aBase + bufC * A_STAGE_B;
        const uint32_t bS = bBase + bufC * A_STAGE_B;
#pragma unroll
        for (int ks = 0; ks < 2; ks++) {
            unsigned af[4][4], bf[8][2];
#pragma unroll
            for (int mt = 0; mt < 4; mt++)
                LDSM_X4(af[mt][0], af[mt][1], af[mt][2], af[mt][3],
                        aS + aoff[mt] + (uint32_t)(ks * 32));
            if (!BTRANS) {
#pragma unroll
                for (int p = 0; p < 4; p++)
                    LDSM_X4(bf[2*p][0], bf[2*p][1], bf[2*p+1][0], bf[2*p+1][1],
                            bS + boff[p] + (uint32_t)(ks * 32));
            } else {
#pragma unroll
                for (int p = 0; p < 4; p++)
                    LDSM_X4_T(bf[2*p][0], bf[2*p][1], bf[2*p+1][0], bf[2*p+1][1],
                              bS + boff[p] + (uint32_t)(ks * 16 * (SBH * 2)));
            }
#pragma unroll
            for (int mt = 0; mt < 4; mt++)
#pragma unroll
                for (int nt = 0; nt < 8; nt++)
                    mma_f16(acc[mt][nt][0], acc[mt][nt][1], acc[mt][nt][2], acc[mt][nt][3],
                            af[mt][0], af[mt][1], af[mt][2], af[mt][3],
                            bf[nt][0], bf[nt][1]);
        }
        bufC = (bufC == STAGES - 1) ? 0 : bufC + 1;
        bufS = (bufS == STAGES - 1) ? 0 : bufS + 1;
    }

    // ---------------- epilogues (compiled per MODE) ----------------
#pragma unroll
    for (int mt = 0; mt < 4; mt++) {
        const int row = rowBase + wm * 64 + mt * 16 + lq;
        float rsum0 = 0.0f, rsum1 = 0.0f;   // MODE_EXP partial sums: row, row+8
#pragma unroll
        for (int nt = 0; nt < 8; nt++) {
            const int col = colBase + wn * 64 + nt * 8 + 2 * lr;
            float v0 = acc[mt][nt][0], v1 = acc[mt][nt][1];
            float v2 = acc[mt][nt][2], v3 = acc[mt][nt][3];
            if (MODE == MODE_QKV) {
                v0 += bias[col]; v1 += bias[col + 1];
                v2 += bias[col]; v3 += bias[col + 1];
                const float s0 = (col     < splitCol) ? scale0 : scale1;
                const float s1 = (col + 1 < splitCol) ? scale0 : scale1;
                v0 *= s0; v1 *= s1; v2 *= s0; v3 *= s1;
                *(__half2*)&Ch[(long long)row * ldc + col]       = __floats2half2_rn(v0, v1);
                *(__half2*)&Ch[(long long)(row + 8) * ldc + col] = __floats2half2_rn(v2, v3);
            } else if (MODE == MODE_EXP) {
                v0 = (row == col)         ? 0.0f : __expf(v0);
                v1 = (row == col + 1)     ? 0.0f : __expf(v1);
                v2 = (row + 8 == col)     ? 0.0f : __expf(v2);
                v3 = (row + 8 == col + 1) ? 0.0f : __expf(v3);
                const __half2 h0 = __floats2half2_rn(v0, v1);
                const __half2 h1 = __floats2half2_rn(v2, v3);
                *(__half2*)&Ch[(long long)row * ldc + col]       = h0;
                *(__half2*)&Ch[(long long)(row + 8) * ldc + col] = h1;
                const float2 f0 = __half22float2(h0);   // sum the rounded values
                const float2 f1 = __half22float2(h1);
                rsum0 += f0.x + f0.y;
                rsum1 += f1.x + f1.y;
            } else { // MODE_AV
                const float r0 = rowScale[(long long)blockIdx.z * M + row];
                const float r1 = rowScale[(long long)blockIdx.z * M + row + 8];
                *(float2*)&Cf[(long long)row * ldc + col]       = make_float2(v0 * r0, v1 * r0);
                *(float2*)&Cf[(long long)(row + 8) * ldc + col] = make_float2(v2 * r1, v3 * r1);
            }
        }
        if (MODE == MODE_EXP) {
            // reduce across the 4 lanes (lr) sharing each row
            rsum0 += __shfl_xor_sync(0xFFFFFFFF, rsum0, 1);
            rsum0 += __shfl_xor_sync(0xFFFFFFFF, rsum0, 2);
            rsum1 += __shfl_xor_sync(0xFFFFFFFF, rsum1, 1);
            rsum1 += __shfl_xor_sync(0xFFFFFFFF, rsum1, 2);
            if (lr == 0) {
                const int part = blockIdx.x * 2 + wn;    // 32 partials per row
                float* rp = rsp + (long long)part * (B_ * L_) + (long long)blockIdx.z * M;
                rp[row]     = rsum0;
                rp[row + 8] = rsum1;
            }
        }
    }
}

// rs[r] = 1 / sum_{p<32} rsp[p][r]
__global__ __launch_bounds__(256) void reduce_rs(const float* __restrict__ rsp,
                                                 float* __restrict__ rs)
{
    const int r = blockIdx.x * blockDim.x + threadIdx.x;
    if (r >= B_ * L_) return;
    float s = 0.0f;
#pragma unroll
    for (int p = 0; p < 32; p++) s += rsp[(long long)p * (B_ * L_) + r];
    rs[r] = 1.0f / s;
}

// Round f32 -> fp16 (rne). Grid-stride, float4 in / 4x half out.
__global__ __launch_bounds__(256) void round_f16(const float* __restrict__ in,
                                                 __half* __restrict__ out, long long n4)
{
    const long long i0 = (long long)blockIdx.x * blockDim.x + threadIdx.x;
    const long long stride = (long long)gridDim.x * blockDim.x;
    for (long long i = i0; i < n4; i += stride) {
        float4 v = ((const float4*)in)[i];
        __half2 h0 = __floats2half2_rn(v.x, v.y);
        __half2 h1 = __floats2half2_rn(v.z, v.w);
        ((uint2*)out)[i] = make_uint2(*(uint32_t*)&h0, *(uint32_t*)&h1);
    }
}

// Round all three weight matrices + pack biases in one launch.
__global__ __launch_bounds__(256) void prep_w(
    const float* __restrict__ Wq, const float* __restrict__ Wk, const float* __restrict__ Wv,
    const float* __restrict__ bq, const float* __restrict__ bk, const float* __restrict__ bv,
    __half* __restrict__ wh, float* __restrict__ bias)
{
    const long long seg4 = (long long)H_ * H_ / 4;
    const long long i0 = (long long)blockIdx.x * blockDim.x + threadIdx.x;
    const long long stride = (long long)gridDim.x * blockDim.x;
    for (long long i = i0; i < 3 * seg4; i += stride) {
        const int seg = (int)(i / seg4);
        const long long loc = i - (long long)seg * seg4;
        const float* src = (seg == 0) ? Wq : (seg == 1) ? Wk : Wv;
        float4 v = ((const float4*)src)[loc];
        __half2 h0 = __floats2half2_rn(v.x, v.y);
        __half2 h1 = __floats2half2_rn(v.z, v.w);
        ((uint2*)wh)[i] = make_uint2(*(uint32_t*)&h0, *(uint32_t*)&h1);
    }
    const int bi = blockIdx.x * blockDim.x + threadIdx.x;
    if (bi < H_)            bias[bi] = bq[bi];
    else if (bi < 2 * H_)   bias[bi] = bk[bi - H_];
    else if (bi < 3 * H_)   bias[bi] = bv[bi - 2 * H_];
}

extern "C" void kernel_launch(void* const* d_in, const int* in_sizes, int n_in,
                              void* d_out, int out_size)
{
    const float* x  = (const float*)d_in[0];
    const float* Wq = (const float*)d_in[1];
    const float* bq = (const float*)d_in[2];
    const float* Wk = (const float*)d_in[3];
    const float* bk = (const float*)d_in[4];
    const float* Wv = (const float*)d_in[5];
    const float* bv = (const float*)d_in[6];
    float* out = (float*)d_out;

    __half *xh, *wh, *qkv, *e;
    float *bias, *rsp, *rs;
    cudaGetSymbolAddress((void**)&xh,   g_xh);
    cudaGetSymbolAddress((void**)&wh,   g_wh);
    cudaGetSymbolAddress((void**)&qkv,  g_qkv);
    cudaGetSymbolAddress((void**)&e,    g_e);
    cudaGetSymbolAddress((void**)&bias, g_bias);
    cudaGetSymbolAddress((void**)&rsp,  g_rsp);
    cudaGetSymbolAddress((void**)&rs,   g_rs);

    cudaFuncSetAttribute(gemm_t<MODE_QKV, 0>, cudaFuncAttributeMaxDynamicSharedMemorySize, NT_SMEM);
    cudaFuncSetAttribute(gemm_t<MODE_EXP, 0>, cudaFuncAttributeMaxDynamicSharedMemorySize, NT_SMEM);
    cudaFuncSetAttribute(gemm_t<MODE_AV, 1>,  cudaFuncAttributeMaxDynamicSharedMemorySize, NT_SMEM);

    const long long sQKV = (long long)L_ * 3 * H_;
    const long long sSS  = (long long)L_ * L_;
    const long long sO   = (long long)L_ * H_;

    // Input prep
    round_f16<<<1024, 256>>>(x, xh, (long long)B_ * L_ * H_ / 4);
    prep_w<<<768, 256>>>(Wq, Wk, Wv, bq, bk, bv, wh, bias);

    const dim3 blk(128);

    // Fused QKV: qkv[r][0:H]=q (scaled 1/H), [H:2H]=k, [2H:3H]=v
    dim3 gQKV(3 * H_ / BNT, (B_ * L_) / BMT, 1);
    gemm_t<MODE_QKV, 0><<<gQKV, blk, NT_SMEM>>>(xh, wh, bias, qkv, nullptr, nullptr, nullptr,
                                                B_ * L_, 3 * H_, H_, H_, H_, 3 * H_,
                                                1.0f / (float)H_, H_, 1.0f, 0, 0, 0);

    // E[b] = exp(q[b]*k[b]^T), diag=0, f16 out; partial row sums -> rsp
    dim3 gS(L_ / BNT, L_ / BMT, B_);
    gemm_t<MODE_EXP, 0><<<gS, blk, NT_SMEM>>>(qkv, qkv + H_, nullptr, e, nullptr, nullptr, rsp,
                                              L_, L_, H_, 3 * H_, 3 * H_, L_,
                                              1.0f, 0, 1.0f, sQKV, sQKV, sSS);

    // rs = 1 / rowsum (32 partials per row)
    reduce_rs<<<(B_ * L_ + 255) / 256, 256>>>(rsp, rs);

    // out[b] = (E[b] * V[b]) * rs  (V N-major, trans-ldmatrix path)
    dim3 gO(H_ / BNT, L_ / BMT, B_);
    gemm_t<MODE_AV, 1><<<gO, blk, NT_SMEM>>>(e, qkv + 2 * H_, nullptr, nullptr, out, rs, nullptr,
                                             L_, H_, L_, L_, 3 * H_, H_,
                                             1.0f, 0, 1.0f, sSS, sQKV, sO);
}